// round 10
// baseline (speedup 1.0000x reference)
#include <cuda_runtime.h>
#include <math.h>

#define En 2
#define NN 512
#define Bn 64
#define Tt 12
#define Kk 64
#define RN 4     // rows per block tile in main kernel
#define BG 8     // batches per block in main kernel
#define ESTR (Bn * NN * NN)   // e-stride in output
#define NTHREADS 288          // 256 compute + 32 reducer

// Scratch (static device arrays: allocation-free)
__device__ __align__(16) float g_sup[En * NN * NN];      // relu(supports + adaptive)  (2 MB)
__device__ __align__(16) float g_nodesT[Bn * NN * Tt];   // normalized nodes, [b][n][t] (1.5 MB)
__device__ __align__(16) float g_nodesN[Bn * Tt * NN];   // normalized nodes, [b][t][n] (1.5 MB)

typedef unsigned long long ull;

// ---------------- packed f32x2 + MUFU helpers ----------------
__device__ __forceinline__ ull pack2(float a, float b) {
    ull r;
    asm("mov.b64 %0, {%1, %2};" : "=l"(r) : "f"(a), "f"(b));
    return r;
}
__device__ __forceinline__ void unpack2(ull p, float& a, float& b) {
    asm("mov.b64 {%0, %1}, %2;" : "=f"(a), "=f"(b) : "l"(p));
}
__device__ __forceinline__ ull fma2_(ull a, ull b, ull c) {
    ull d;
    asm("fma.rn.f32x2 %0, %1, %2, %3;" : "=l"(d) : "l"(a), "l"(b), "l"(c));
    return d;
}
__device__ __forceinline__ ull mul2_(ull a, ull b) {
    ull d;
    asm("mul.rn.f32x2 %0, %1, %2;" : "=l"(d) : "l"(a), "l"(b));
    return d;
}
__device__ __forceinline__ ull add2_(ull a, ull b) {
    ull d;
    asm("add.rn.f32x2 %0, %1, %2;" : "=l"(d) : "l"(a), "l"(b));
    return d;
}
__device__ __forceinline__ float sqrt_ap(float x) { float r; asm("sqrt.approx.f32 %0, %1;" : "=f"(r) : "f"(x)); return r; }
__device__ __forceinline__ float ex2_neg(float x) { float r; asm("ex2.approx.f32 %0, %1;"  : "=f"(r) : "f"(-x)); return r; }
__device__ __forceinline__ float rcp_ap(float x)  { float r; asm("rcp.approx.f32 %0, %1;"  : "=f"(r) : "f"(x)); return r; }
__device__ __forceinline__ float hadd2(ull p) {
    float a, b; unpack2(p, a, b); return a + b;
}
__device__ __forceinline__ ull shfl_xor64(ull v, int o) {
    unsigned lo = (unsigned)v, hi = (unsigned)(v >> 32);
    lo = __shfl_xor_sync(0xffffffffu, lo, o);
    hi = __shfl_xor_sync(0xffffffffu, hi, o);
    return ((ull)hi << 32) | lo;
}

#define BAR_SYNC(id)   asm volatile("bar.sync %0, %1;"   :: "n"(id), "n"(NTHREADS) : "memory")
#define BAR_ARRIVE(id) asm volatile("bar.arrive %0, %1;" :: "n"(id), "n"(NTHREADS) : "memory")

// ---------------------------------------------------------------------------
// Kernel A (fused prep), 256 threads:
//   z = 0,1 : g_sup[e] = relu(supports + u * diag(s*softplus(bias)) * v^T)
//             32(n) x 64(m) tile, 2x4 micro-tile  (grid 8 x 16)
//   z = 2   : L2-normalize node histories -> g_nodesT [b][n][t] + g_nodesN [b][t][n]
// ---------------------------------------------------------------------------
__global__ void __launch_bounds__(256) prep_kernel(const float* __restrict__ supports,
                                                   const float* __restrict__ u,
                                                   const float* __restrict__ s,
                                                   const float* __restrict__ v,
                                                   const float* __restrict__ bias,
                                                   const float* __restrict__ inputs) {
    const int tid = threadIdx.x;

    if (blockIdx.z == 2) {
        // ---- nodes path: 128 blocks x 256 threads, 1 item each ----
        const int i = (blockIdx.y * 8 + blockIdx.x) * 256 + tid;  // b*512 + n
        const int b = i >> 9, n = i & (NN - 1);
        float x[Tt];
        float ss = 0.f;
        #pragma unroll
        for (int t = 0; t < Tt; t++) {
            x[t] = inputs[(((b * Tt + t) * NN) + n) * 2];
            ss = fmaf(x[t], x[t], ss);
        }
        float inv = 1.0f / fmaxf(sqrtf(ss), 1e-12f);
        #pragma unroll
        for (int t = 0; t < Tt; t++) x[t] *= inv;
        float* dst = g_nodesT + (b * NN + n) * Tt;
        *(float4*)(dst)     = make_float4(x[0], x[1], x[2],  x[3]);
        *(float4*)(dst + 4) = make_float4(x[4], x[5], x[6],  x[7]);
        *(float4*)(dst + 8) = make_float4(x[8], x[9], x[10], x[11]);
        #pragma unroll
        for (int t = 0; t < Tt; t++)
            g_nodesN[(b * Tt + t) * NN + n] = x[t];
        return;
    }

    __shared__ float su_t[Kk][36];   // [k][n-row], scaled; 32 rows + pad
    __shared__ float sv_t[Kk][68];   // [k][m-row]; 64 rows + pad
    __shared__ float ssc[Kk];

    const int e  = blockIdx.z;
    const int n0 = blockIdx.y * 32;
    const int m0 = blockIdx.x * 64;

    if (tid < 64) {
        float bx = bias[e * Kk + tid];
        float sp = (bx > 20.f) ? bx : log1pf(__expf(bx));   // softplus
        ssc[tid] = s[e * Kk + tid] * sp;
    }
    __syncthreads();

    // u tile: 32 rows x 64 k = 512 float4 (2 per thread), transposed store
    #pragma unroll
    for (int j = 0; j < 2; j++) {
        int idx = tid + j * 256;
        int row = idx & 31;
        int kq  = idx >> 5;        // 0..15
        float4 uv = *(const float4*)(u + (e * NN + n0 + row) * Kk + kq * 4);
        su_t[kq * 4 + 0][row] = uv.x * ssc[kq * 4 + 0];
        su_t[kq * 4 + 1][row] = uv.y * ssc[kq * 4 + 1];
        su_t[kq * 4 + 2][row] = uv.z * ssc[kq * 4 + 2];
        su_t[kq * 4 + 3][row] = uv.w * ssc[kq * 4 + 3];
    }
    // v tile: 64 rows x 64 k = 1024 float4 (4 per thread)
    #pragma unroll
    for (int j = 0; j < 4; j++) {
        int idx = tid + j * 256;
        int row = idx & 63;
        int kq  = idx >> 6;        // 0..15
        float4 vv = *(const float4*)(v + (e * NN + m0 + row) * Kk + kq * 4);
        sv_t[kq * 4 + 0][row] = vv.x;
        sv_t[kq * 4 + 1][row] = vv.y;
        sv_t[kq * 4 + 2][row] = vv.z;
        sv_t[kq * 4 + 3][row] = vv.w;
    }
    __syncthreads();

    const int ry = (tid >> 4) << 1;       // 0..30
    const int rx = (tid & 15) << 2;       // 0..60
    float acc[2][4] = {};

    #pragma unroll
    for (int k = 0; k < 64; k++) {
        float2 a  = *(const float2*)&su_t[k][ry];
        float4 bq = *(const float4*)&sv_t[k][rx];
        acc[0][0] = fmaf(a.x, bq.x, acc[0][0]); acc[0][1] = fmaf(a.x, bq.y, acc[0][1]);
        acc[0][2] = fmaf(a.x, bq.z, acc[0][2]); acc[0][3] = fmaf(a.x, bq.w, acc[0][3]);
        acc[1][0] = fmaf(a.y, bq.x, acc[1][0]); acc[1][1] = fmaf(a.y, bq.y, acc[1][1]);
        acc[1][2] = fmaf(a.y, bq.z, acc[1][2]); acc[1][3] = fmaf(a.y, bq.w, acc[1][3]);
    }

    #pragma unroll
    for (int i = 0; i < 2; i++) {
        int base = (e * NN + n0 + ry + i) * NN + m0 + rx;
        float4 sp = *(const float4*)(supports + base);
        float4 o;
        o.x = fmaxf(sp.x + acc[i][0], 0.f);
        o.y = fmaxf(sp.y + acc[i][1], 0.f);
        o.z = fmaxf(sp.z + acc[i][2], 0.f);
        o.w = fmaxf(sp.w + acc[i][3], 0.f);
        *(float4*)(g_sup + base) = o;
    }
}

// ---------------------------------------------------------------------------
// Kernel C: fused main pass, warp-specialized.
// 288 threads: tid 0..255 compute (one m-pair each), tid 256..287 = reducer warp.
// Named barriers: bar1 = ps ready (computers arrive, reducer syncs);
//                 bar2 = invs ready (reducer arrives, computers sync).
// Writeout is one batch delayed -> reduce latency fully hidden.
// ---------------------------------------------------------------------------
__global__ void __launch_bounds__(NTHREADS, 2)
main_kernel(float* __restrict__ out) {
    __shared__ __align__(16) ull ps[2][RN][256];   // packed {e0,e1} partials, dbl-buffered
    __shared__ ull xd[BG * RN * Tt];               // packed {xn,xn}, all batches
    __shared__ ull invs[2][RN];                    // packed {iv_e0, iv_e1}

    const int tid = threadIdx.x;
    const int n0 = blockIdx.x * RN;
    const int b0 = blockIdx.y * BG;

    // Stage duplicated row-node tables for ALL batches (384 entries)
    for (int i = tid; i < BG * RN * Tt; i += NTHREADS) {
        int bl  = i / (RN * Tt);
        int rem = i - bl * (RN * Tt);
        int r = rem / Tt, t = rem - r * Tt;
        float xv = g_nodesT[(b0 + bl) * (NN * Tt) + (n0 + r) * Tt + t];
        xd[i] = pack2(xv, xv);
    }
    __syncthreads();

    if (tid < 256) {
        // ================= compute warps =================
        const int m0 = tid * 2;

        ull sup0[RN], sup1[RN];
        #pragma unroll
        for (int r = 0; r < RN; r++) {
            sup0[r] = *(const ull*)(g_sup + (n0 + r) * NN + m0);
            sup1[r] = *(const ull*)(g_sup + NN * NN + (n0 + r) * NN + m0);
        }

        // 2 * (ln2^-1)^2
        const float C = 4.1627379620112154f;
        const ull CM = pack2(-C, -C);
        const ull CP = pack2( C,  C);

        ull val0[RN], val1[RN];

        #pragma unroll 2
        for (int bi = 0; bi < BG; ++bi) {
            const int cur = bi & 1;

            // 1) this batch's xm2 loads first (12 coalesced LDG.64)
            ull xm2[Tt];
            {
                const ull* xb = (const ull*)(g_nodesN + (b0 + bi) * (Tt * NN)) + tid;
                #pragma unroll
                for (int t = 0; t < Tt; t++)
                    xm2[t] = xb[t * (NN / 2)];
            }

            // 2) previous batch's writeout, gated on reducer's invs
            if (bi > 0) {
                BAR_SYNC(2);
                const int pv = (bi - 1) & 1;
                float* ob = out + ((b0 + bi - 1) * NN + n0) * NN + m0;
                #pragma unroll
                for (int r = 0; r < RN; r++) {
                    float iv0, iv1;
                    unpack2(invs[pv][r], iv0, iv1);
                    *(ull*)(ob + r * NN)        = mul2_(val0[r], pack2(iv0, iv0));
                    *(ull*)(ob + ESTR + r * NN) = mul2_(val1[r], pack2(iv1, iv1));
                }
            }

            // 3) compute vals + packed partial sums into ps[cur]
            #pragma unroll
            for (int r = 0; r < RN; r++) {
                const ulonglong2* xdp = (const ulonglong2*)&xd[(bi * RN + r) * Tt];
                ulonglong2 q0 = xdp[0], q1 = xdp[1], q2 = xdp[2];
                ulonglong2 q3 = xdp[3], q4 = xdp[4], q5 = xdp[5];
                ull pa = mul2_(xm2[0], q0.x);
                ull pb = mul2_(xm2[1], q0.y);
                pa = fma2_(xm2[2],  q1.x, pa);  pb = fma2_(xm2[3],  q1.y, pb);
                pa = fma2_(xm2[4],  q2.x, pa);  pb = fma2_(xm2[5],  q2.y, pb);
                pa = fma2_(xm2[6],  q3.x, pa);  pb = fma2_(xm2[7],  q3.y, pb);
                pa = fma2_(xm2[8],  q4.x, pa);  pb = fma2_(xm2[9],  q4.y, pb);
                pa = fma2_(xm2[10], q5.x, pa);  pb = fma2_(xm2[11], q5.y, pb);
                ull inner2 = add2_(pa, pb);
                ull d2p = fma2_(inner2, CM, CP);  // (1.4427*d)^2 packed
                float d20, d21;
                unpack2(d2p, d20, d21);
                d20 = fmaxf(d20, 0.f);
                d21 = fmaxf(d21, 0.f);
                float f0 = ex2_neg(sqrt_ap(d20)) + 1.0f;
                float f1 = ex2_neg(sqrt_ap(d21)) + 1.0f;
                ull fp = pack2(f0, f1);

                val0[r] = mul2_(fp, sup0[r]);
                val1[r] = mul2_(fp, sup1[r]);
                ps[cur][r][tid] = pack2(hadd2(val0[r]), hadd2(val1[r]));
            }
            BAR_ARRIVE(1);      // ps[cur] ready for reducer
        }

        // Epilogue: last batch's writeout
        BAR_SYNC(2);
        {
            const int pv = (BG - 1) & 1;
            float* ob = out + ((b0 + BG - 1) * NN + n0) * NN + m0;
            #pragma unroll
            for (int r = 0; r < RN; r++) {
                float iv0, iv1;
                unpack2(invs[pv][r], iv0, iv1);
                *(ull*)(ob + r * NN)        = mul2_(val0[r], pack2(iv0, iv0));
                *(ull*)(ob + ESTR + r * NN) = mul2_(val1[r], pack2(iv1, iv1));
            }
        }
    } else {
        // ================= reducer warp =================
        const int lane = tid & 31;

        #pragma unroll 2
        for (int bi = 0; bi < BG; ++bi) {
            const int cur = bi & 1;
            BAR_SYNC(1);        // wait for ps[cur]

            #pragma unroll
            for (int r = 0; r < RN; r++) {
                const ulonglong2* p = (const ulonglong2*)ps[cur][r];
                ulonglong2 a0 = p[lane];
                ulonglong2 a1 = p[lane + 32];
                ulonglong2 a2 = p[lane + 64];
                ulonglong2 a3 = p[lane + 96];
                ull s01 = add2_(add2_(a0.x, a0.y), add2_(a1.x, a1.y));
                ull s23 = add2_(add2_(a2.x, a2.y), add2_(a3.x, a3.y));
                ull sum = add2_(s01, s23);
                #pragma unroll
                for (int o = 16; o > 0; o >>= 1)
                    sum = add2_(sum, shfl_xor64(sum, o));
                if (lane == 0) {
                    float s0, s1;
                    unpack2(sum, s0, s1);
                    invs[cur][r] = pack2(rcp_ap(fmaxf(s0, 1e-12f)),
                                         rcp_ap(fmaxf(s1, 1e-12f)));
                }
            }
            BAR_ARRIVE(2);      // invs[cur] ready for computers
        }
    }
}

// ---------------------------------------------------------------------------
extern "C" void kernel_launch(void* const* d_in, const int* in_sizes, int n_in,
                              void* d_out, int out_size) {
    const float* supports = (const float*)d_in[0];  // [2,512,512]
    const float* u        = (const float*)d_in[1];  // [2,512,64]
    const float* s        = (const float*)d_in[2];  // [2,64]
    const float* v        = (const float*)d_in[3];  // [2,512,64]
    const float* bias     = (const float*)d_in[4];  // [2,64]
    const float* inputs   = (const float*)d_in[5];  // [64,12,512,2]
    float* out = (float*)d_out;                     // [2,64,512,512]

    prep_kernel<<<dim3(8, 16, 3), 256>>>(supports, u, s, v, bias, inputs);
    main_kernel<<<dim3(NN / RN, Bn / BG), NTHREADS>>>(out);
}

// round 11
// speedup vs baseline: 1.2582x; 1.2582x over previous
#include <cuda_runtime.h>
#include <math.h>

#define En 2
#define NN 512
#define Bn 64
#define Tt 12
#define Kk 64
#define RN 4     // rows per block tile in main kernel
#define BG 8     // batches per block in main kernel
#define ESTR (Bn * NN * NN)   // e-stride in output

// Scratch (static device arrays: allocation-free)
__device__ __align__(16) float g_sup[En * NN * NN];      // relu(supports + adaptive)  (2 MB)
__device__ __align__(16) float g_nodesT[Bn * NN * Tt];   // normalized nodes, [b][n][t] (1.5 MB)
__device__ __align__(16) float g_nodesN[Bn * Tt * NN];   // normalized nodes, [b][t][n] (1.5 MB)

typedef unsigned long long ull;

// ---------------- packed f32x2 + MUFU helpers ----------------
__device__ __forceinline__ ull pack2(float a, float b) {
    ull r;
    asm("mov.b64 %0, {%1, %2};" : "=l"(r) : "f"(a), "f"(b));
    return r;
}
__device__ __forceinline__ void unpack2(ull p, float& a, float& b) {
    asm("mov.b64 {%0, %1}, %2;" : "=f"(a), "=f"(b) : "l"(p));
}
__device__ __forceinline__ ull fma2_(ull a, ull b, ull c) {
    ull d;
    asm("fma.rn.f32x2 %0, %1, %2, %3;" : "=l"(d) : "l"(a), "l"(b), "l"(c));
    return d;
}
__device__ __forceinline__ ull mul2_(ull a, ull b) {
    ull d;
    asm("mul.rn.f32x2 %0, %1, %2;" : "=l"(d) : "l"(a), "l"(b));
    return d;
}
__device__ __forceinline__ ull add2_(ull a, ull b) {
    ull d;
    asm("add.rn.f32x2 %0, %1, %2;" : "=l"(d) : "l"(a), "l"(b));
    return d;
}
__device__ __forceinline__ float sqrt_ap(float x) { float r; asm("sqrt.approx.f32 %0, %1;" : "=f"(r) : "f"(x)); return r; }
__device__ __forceinline__ float ex2_neg(float x) { float r; asm("ex2.approx.f32 %0, %1;"  : "=f"(r) : "f"(-x)); return r; }
__device__ __forceinline__ float rcp_ap(float x)  { float r; asm("rcp.approx.f32 %0, %1;"  : "=f"(r) : "f"(x)); return r; }
__device__ __forceinline__ float hadd2(ull p) {
    float a, b; unpack2(p, a, b); return a + b;
}
__device__ __forceinline__ ull shfl_xor64(ull v, int o) {
    unsigned lo = (unsigned)v, hi = (unsigned)(v >> 32);
    lo = __shfl_xor_sync(0xffffffffu, lo, o);
    hi = __shfl_xor_sync(0xffffffffu, hi, o);
    return ((ull)hi << 32) | lo;
}

// ---------------------------------------------------------------------------
// Kernel A (fused prep), 512 threads:
//   z = 0,1 : g_sup[e] = relu(supports + u * diag(s*softplus(bias)) * v^T)
//   z = 2   : L2-normalize node histories -> g_nodesT [b][n][t] + g_nodesN [b][t][n]
// ---------------------------------------------------------------------------
__global__ void __launch_bounds__(512) prep_kernel(const float* __restrict__ supports,
                                                   const float* __restrict__ u,
                                                   const float* __restrict__ s,
                                                   const float* __restrict__ v,
                                                   const float* __restrict__ bias,
                                                   const float* __restrict__ inputs) {
    const int tid = threadIdx.x;

    if (blockIdx.z == 2) {
        const int i = (blockIdx.y * 8 + blockIdx.x) * 512 + tid;  // b*512 + n
        const int b = i >> 9, n = i & (NN - 1);
        float x[Tt];
        float ss = 0.f;
        #pragma unroll
        for (int t = 0; t < Tt; t++) {
            x[t] = inputs[(((b * Tt + t) * NN) + n) * 2];
            ss = fmaf(x[t], x[t], ss);
        }
        float inv = 1.0f / fmaxf(sqrtf(ss), 1e-12f);
        #pragma unroll
        for (int t = 0; t < Tt; t++) x[t] *= inv;
        float* dst = g_nodesT + (b * NN + n) * Tt;
        *(float4*)(dst)     = make_float4(x[0], x[1], x[2],  x[3]);
        *(float4*)(dst + 4) = make_float4(x[4], x[5], x[6],  x[7]);
        *(float4*)(dst + 8) = make_float4(x[8], x[9], x[10], x[11]);
        #pragma unroll
        for (int t = 0; t < Tt; t++)
            g_nodesN[(b * Tt + t) * NN + n] = x[t];
        return;
    }

    __shared__ float su_t[Kk][68];
    __shared__ float sv_t[Kk][68];
    __shared__ float ssc[Kk];

    const int e  = blockIdx.z;
    const int n0 = blockIdx.y * 64;
    const int m0 = blockIdx.x * 64;

    if (tid < 64) {
        float bx = bias[e * Kk + tid];
        float sp = (bx > 20.f) ? bx : log1pf(__expf(bx));   // softplus
        ssc[tid] = s[e * Kk + tid] * sp;
    }
    __syncthreads();

    #pragma unroll
    for (int j = 0; j < 2; j++) {
        int idx = tid + j * 512;
        int row = idx & 63;
        int kq  = idx >> 6;
        float4 uv = *(const float4*)(u + (e * NN + n0 + row) * Kk + kq * 4);
        float4 vv = *(const float4*)(v + (e * NN + m0 + row) * Kk + kq * 4);
        su_t[kq * 4 + 0][row] = uv.x * ssc[kq * 4 + 0];
        su_t[kq * 4 + 1][row] = uv.y * ssc[kq * 4 + 1];
        su_t[kq * 4 + 2][row] = uv.z * ssc[kq * 4 + 2];
        su_t[kq * 4 + 3][row] = uv.w * ssc[kq * 4 + 3];
        sv_t[kq * 4 + 0][row] = vv.x;
        sv_t[kq * 4 + 1][row] = vv.y;
        sv_t[kq * 4 + 2][row] = vv.z;
        sv_t[kq * 4 + 3][row] = vv.w;
    }
    __syncthreads();

    const int ry = (tid >> 4) << 1;
    const int rx = (tid & 15) << 2;
    float acc[2][4] = {};

    #pragma unroll
    for (int k = 0; k < 64; k++) {
        float2 a  = *(const float2*)&su_t[k][ry];
        float4 bq = *(const float4*)&sv_t[k][rx];
        acc[0][0] = fmaf(a.x, bq.x, acc[0][0]); acc[0][1] = fmaf(a.x, bq.y, acc[0][1]);
        acc[0][2] = fmaf(a.x, bq.z, acc[0][2]); acc[0][3] = fmaf(a.x, bq.w, acc[0][3]);
        acc[1][0] = fmaf(a.y, bq.x, acc[1][0]); acc[1][1] = fmaf(a.y, bq.y, acc[1][1]);
        acc[1][2] = fmaf(a.y, bq.z, acc[1][2]); acc[1][3] = fmaf(a.y, bq.w, acc[1][3]);
    }

    #pragma unroll
    for (int i = 0; i < 2; i++) {
        int base = (e * NN + n0 + ry + i) * NN + m0 + rx;
        float4 sp = *(const float4*)(supports + base);
        float4 o;
        o.x = fmaxf(sp.x + acc[i][0], 0.f);
        o.y = fmaxf(sp.y + acc[i][1], 0.f);
        o.z = fmaxf(sp.z + acc[i][2], 0.f);
        o.w = fmaxf(sp.w + acc[i][3], 0.f);
        *(float4*)(g_sup + base) = o;
    }
}

// ---------------------------------------------------------------------------
// Kernel C: fused main pass (R8 structure, BG=8, PDL-gated).
// RN=4 rows x BOTH experts; xd staged once for all BG batches;
// xm2 LDGs issued before prev-batch writeout (latency shadow);
// 2 barriers per batch; invs stored pre-duplicated {iv,iv} per expert.
// ---------------------------------------------------------------------------
__global__ void __launch_bounds__(256, 3)
main_kernel(float* __restrict__ out) {
    __shared__ ull ps[RN][256];                  // packed {e0,e1} partials, 8 KB
    __shared__ ull xd[BG * RN * Tt];             // packed {xn,xn}, all batches (3 KB)
    __shared__ ull invs0[2][RN];                 // {iv_e0, iv_e0}, dbl-buffered
    __shared__ ull invs1[2][RN];                 // {iv_e1, iv_e1}, dbl-buffered

    // PDL: wait for prep_kernel's writes (g_sup, g_nodesT, g_nodesN)
    cudaGridDependencySynchronize();

    const int tid  = threadIdx.x;
    const int lane = tid & 31;
    const int warp = tid >> 5;
    const int n0 = blockIdx.x * RN;
    const int b0 = blockIdx.y * BG;
    const int m0 = tid * 2;

    // sup (relu'd) in registers: batch-invariant, this thread's m-pair, both e
    ull sup0[RN], sup1[RN];
    #pragma unroll
    for (int r = 0; r < RN; r++) {
        sup0[r] = *(const ull*)(g_sup + (n0 + r) * NN + m0);
        sup1[r] = *(const ull*)(g_sup + NN * NN + (n0 + r) * NN + m0);
    }

    // Stage duplicated row-node tables for ALL batches (384 entries)
    for (int i = tid; i < BG * RN * Tt; i += 256) {
        int bl  = i / (RN * Tt);
        int rem = i - bl * (RN * Tt);
        int r = rem / Tt, t = rem - r * Tt;
        float xv = g_nodesT[(b0 + bl) * (NN * Tt) + (n0 + r) * Tt + t];
        xd[i] = pack2(xv, xv);
    }
    __syncthreads();

    // 2 * (ln2^-1)^2
    const float C = 4.1627379620112154f;
    const ull CM = pack2(-C, -C);
    const ull CP = pack2( C,  C);

    ull val0[RN], val1[RN];

    #pragma unroll 2
    for (int bi = 0; bi < BG; ++bi) {
        // 1) issue this batch's xm2 loads FIRST (12 coalesced LDG.64)
        ull xm2[Tt];
        {
            const ull* xb = (const ull*)(g_nodesN + (b0 + bi) * (Tt * NN)) + tid;
            #pragma unroll
            for (int t = 0; t < Tt; t++)
                xm2[t] = xb[t * (NN / 2)];
        }

        // 2) previous batch's writeout in the LDG shadow
        if (bi > 0) {
            const int pv = (bi - 1) & 1;
            float* ob = out + ((b0 + bi - 1) * NN + n0) * NN + m0;
            #pragma unroll
            for (int r = 0; r < RN; r++) {
                *(ull*)(ob + r * NN)        = mul2_(val0[r], invs0[pv][r]);
                *(ull*)(ob + ESTR + r * NN) = mul2_(val1[r], invs1[pv][r]);
            }
        }

        // 3) compute vals + packed partial sums
        #pragma unroll
        for (int r = 0; r < RN; r++) {
            const ulonglong2* xdp = (const ulonglong2*)&xd[(bi * RN + r) * Tt];
            ulonglong2 q0 = xdp[0], q1 = xdp[1], q2 = xdp[2];
            ulonglong2 q3 = xdp[3], q4 = xdp[4], q5 = xdp[5];
            ull pa = mul2_(xm2[0], q0.x);
            ull pb = mul2_(xm2[1], q0.y);
            pa = fma2_(xm2[2],  q1.x, pa);  pb = fma2_(xm2[3],  q1.y, pb);
            pa = fma2_(xm2[4],  q2.x, pa);  pb = fma2_(xm2[5],  q2.y, pb);
            pa = fma2_(xm2[6],  q3.x, pa);  pb = fma2_(xm2[7],  q3.y, pb);
            pa = fma2_(xm2[8],  q4.x, pa);  pb = fma2_(xm2[9],  q4.y, pb);
            pa = fma2_(xm2[10], q5.x, pa);  pb = fma2_(xm2[11], q5.y, pb);
            ull inner2 = add2_(pa, pb);
            ull d2p = fma2_(inner2, CM, CP);  // (1.4427*d)^2 packed
            float d20, d21;
            unpack2(d2p, d20, d21);
            d20 = fmaxf(d20, 0.f);
            d21 = fmaxf(d21, 0.f);
            float f0 = ex2_neg(sqrt_ap(d20)) + 1.0f;
            float f1 = ex2_neg(sqrt_ap(d21)) + 1.0f;
            ull fp = pack2(f0, f1);

            val0[r] = mul2_(fp, sup0[r]);
            val1[r] = mul2_(fp, sup1[r]);
            ps[r][tid] = pack2(hadd2(val0[r]), hadd2(val1[r]));
        }
        __syncthreads();   // ps ready

        // 4) packed reduction: warps 0..RN-1 each reduce one row (256 ulls)
        if (warp < RN) {
            const ulonglong2* p = (const ulonglong2*)ps[warp];
            ulonglong2 a0 = p[lane];
            ulonglong2 a1 = p[lane + 32];
            ulonglong2 a2 = p[lane + 64];
            ulonglong2 a3 = p[lane + 96];
            ull s01 = add2_(add2_(a0.x, a0.y), add2_(a1.x, a1.y));
            ull s23 = add2_(add2_(a2.x, a2.y), add2_(a3.x, a3.y));
            ull sum = add2_(s01, s23);
            #pragma unroll
            for (int o = 16; o > 0; o >>= 1)
                sum = add2_(sum, shfl_xor64(sum, o));
            if (lane == 0) {
                float s0, s1;
                unpack2(sum, s0, s1);
                float i0 = rcp_ap(fmaxf(s0, 1e-12f));
                float i1 = rcp_ap(fmaxf(s1, 1e-12f));
                invs0[bi & 1][warp] = pack2(i0, i0);
                invs1[bi & 1][warp] = pack2(i1, i1);
            }
        }
        __syncthreads();   // invs ready; guards ps reuse next iter
    }

    // Epilogue: last batch's writeout
    {
        const int pv = (BG - 1) & 1;
        float* ob = out + ((b0 + BG - 1) * NN + n0) * NN + m0;
        #pragma unroll
        for (int r = 0; r < RN; r++) {
            *(ull*)(ob + r * NN)        = mul2_(val0[r], invs0[pv][r]);
            *(ull*)(ob + ESTR + r * NN) = mul2_(val1[r], invs1[pv][r]);
        }
    }
}

// ---------------------------------------------------------------------------
extern "C" void kernel_launch(void* const* d_in, const int* in_sizes, int n_in,
                              void* d_out, int out_size) {
    const float* supports = (const float*)d_in[0];  // [2,512,512]
    const float* u        = (const float*)d_in[1];  // [2,512,64]
    const float* s        = (const float*)d_in[2];  // [2,64]
    const float* v        = (const float*)d_in[3];  // [2,512,64]
    const float* bias     = (const float*)d_in[4];  // [2,64]
    const float* inputs   = (const float*)d_in[5];  // [64,12,512,2]
    float* out = (float*)d_out;                     // [2,64,512,512]

    prep_kernel<<<dim3(8, 8, 3), 512>>>(supports, u, s, v, bias, inputs);

    // Launch main with programmatic dependent launch: it may begin ramping
    // while prep drains; cudaGridDependencySynchronize() in-kernel gates
    // all consumption of prep's outputs.
    cudaLaunchConfig_t cfg = {};
    cfg.gridDim  = dim3(NN / RN, Bn / BG);
    cfg.blockDim = dim3(256);
    cudaLaunchAttribute attr[1];
    attr[0].id = cudaLaunchAttributeProgrammaticStreamSerialization;
    attr[0].val.programmaticStreamSerializationAllowed = 1;
    cfg.attrs = attr;
    cfg.numAttrs = 1;
    cudaLaunchKernelEx(&cfg, main_kernel, out);
}

// round 12
// speedup vs baseline: 1.3381x; 1.0635x over previous
#include <cuda_runtime.h>
#include <math.h>

#define En 2
#define NN 512
#define Bn 64
#define Tt 12
#define Kk 64
#define RN 4     // rows per block tile in main kernel
#define BG 4     // batches per block in main kernel
#define ESTR (Bn * NN * NN)   // e-stride in output

// Scratch (static device arrays: allocation-free)
__device__ __align__(16) float g_sup[En * NN * NN];      // relu(supports + adaptive)  (2 MB)
__device__ __align__(16) float g_nodesT[Bn * NN * Tt];   // normalized nodes, [b][n][t] (1.5 MB)
__device__ __align__(16) float g_nodesP[Bn * Tt * NN];   // pair-packed: [b][t/2][n/2] float4 (1.5 MB)

typedef unsigned long long ull;

// ---------------- packed f32x2 + MUFU helpers ----------------
__device__ __forceinline__ ull pack2(float a, float b) {
    ull r;
    asm("mov.b64 %0, {%1, %2};" : "=l"(r) : "f"(a), "f"(b));
    return r;
}
__device__ __forceinline__ void unpack2(ull p, float& a, float& b) {
    asm("mov.b64 {%0, %1}, %2;" : "=f"(a), "=f"(b) : "l"(p));
}
__device__ __forceinline__ ull fma2_(ull a, ull b, ull c) {
    ull d;
    asm("fma.rn.f32x2 %0, %1, %2, %3;" : "=l"(d) : "l"(a), "l"(b), "l"(c));
    return d;
}
__device__ __forceinline__ ull mul2_(ull a, ull b) {
    ull d;
    asm("mul.rn.f32x2 %0, %1, %2;" : "=l"(d) : "l"(a), "l"(b));
    return d;
}
__device__ __forceinline__ ull add2_(ull a, ull b) {
    ull d;
    asm("add.rn.f32x2 %0, %1, %2;" : "=l"(d) : "l"(a), "l"(b));
    return d;
}
__device__ __forceinline__ float sqrt_ap(float x) { float r; asm("sqrt.approx.f32 %0, %1;" : "=f"(r) : "f"(x)); return r; }
__device__ __forceinline__ float ex2_neg(float x) { float r; asm("ex2.approx.f32 %0, %1;"  : "=f"(r) : "f"(-x)); return r; }
__device__ __forceinline__ float rcp_ap(float x)  { float r; asm("rcp.approx.f32 %0, %1;"  : "=f"(r) : "f"(x)); return r; }
__device__ __forceinline__ float hadd2(ull p) {
    float a, b; unpack2(p, a, b); return a + b;
}
__device__ __forceinline__ ull shfl_xor64(ull v, int o) {
    unsigned lo = (unsigned)v, hi = (unsigned)(v >> 32);
    lo = __shfl_xor_sync(0xffffffffu, lo, o);
    hi = __shfl_xor_sync(0xffffffffu, hi, o);
    return ((ull)hi << 32) | lo;
}

// ---------------------------------------------------------------------------
// Kernel A (fused prep), 512 threads:
//   z = 0,1 : g_sup[e] = relu(supports + u * diag(s*softplus(bias)) * v^T)
//   z = 2   : L2-normalize node histories -> g_nodesT [b][n][t]
//             + g_nodesP [b][6][256] float4 (pair-packed {x2j(m0),x2j(m1),
//               x2j+1(m0),x2j+1(m1)} via shfl exchange)
// ---------------------------------------------------------------------------
__global__ void __launch_bounds__(512) prep_kernel(const float* __restrict__ supports,
                                                   const float* __restrict__ u,
                                                   const float* __restrict__ s,
                                                   const float* __restrict__ v,
                                                   const float* __restrict__ bias,
                                                   const float* __restrict__ inputs) {
    const int tid = threadIdx.x;

    if (blockIdx.z == 2) {
        const int i = (blockIdx.y * 8 + blockIdx.x) * 512 + tid;  // b*512 + n
        const int b = i >> 9, n = i & (NN - 1);
        float x[Tt];
        float ss = 0.f;
        #pragma unroll
        for (int t = 0; t < Tt; t++) {
            x[t] = inputs[(((b * Tt + t) * NN) + n) * 2];
            ss = fmaf(x[t], x[t], ss);
        }
        float inv = 1.0f / fmaxf(sqrtf(ss), 1e-12f);
        #pragma unroll
        for (int t = 0; t < Tt; t++) x[t] *= inv;

        // [b][n][t] layout (for xd staging in main)
        float* dst = g_nodesT + (b * NN + n) * Tt;
        *(float4*)(dst)     = make_float4(x[0], x[1], x[2],  x[3]);
        *(float4*)(dst + 4) = make_float4(x[4], x[5], x[6],  x[7]);
        *(float4*)(dst + 8) = make_float4(x[8], x[9], x[10], x[11]);

        // pair-packed layout: exchange with partner node (n^1) via shfl
        float px[Tt];
        #pragma unroll
        for (int t = 0; t < Tt; t++)
            px[t] = __shfl_xor_sync(0xffffffffu, x[t], 1);
        if ((n & 1) == 0) {
            float4* pd = (float4*)g_nodesP + (b * 6) * 256 + (n >> 1);
            #pragma unroll
            for (int j = 0; j < 6; j++)
                pd[j * 256] = make_float4(x[2 * j], px[2 * j],
                                          x[2 * j + 1], px[2 * j + 1]);
        }
        return;
    }

    __shared__ float su_t[Kk][68];
    __shared__ float sv_t[Kk][68];
    __shared__ float ssc[Kk];

    const int e  = blockIdx.z;
    const int n0 = blockIdx.y * 64;
    const int m0 = blockIdx.x * 64;

    if (tid < 64) {
        float bx = bias[e * Kk + tid];
        float sp = (bx > 20.f) ? bx : log1pf(__expf(bx));   // softplus
        ssc[tid] = s[e * Kk + tid] * sp;
    }
    __syncthreads();

    #pragma unroll
    for (int j = 0; j < 2; j++) {
        int idx = tid + j * 512;
        int row = idx & 63;
        int kq  = idx >> 6;
        float4 uv = *(const float4*)(u + (e * NN + n0 + row) * Kk + kq * 4);
        float4 vv = *(const float4*)(v + (e * NN + m0 + row) * Kk + kq * 4);
        su_t[kq * 4 + 0][row] = uv.x * ssc[kq * 4 + 0];
        su_t[kq * 4 + 1][row] = uv.y * ssc[kq * 4 + 1];
        su_t[kq * 4 + 2][row] = uv.z * ssc[kq * 4 + 2];
        su_t[kq * 4 + 3][row] = uv.w * ssc[kq * 4 + 3];
        sv_t[kq * 4 + 0][row] = vv.x;
        sv_t[kq * 4 + 1][row] = vv.y;
        sv_t[kq * 4 + 2][row] = vv.z;
        sv_t[kq * 4 + 3][row] = vv.w;
    }
    __syncthreads();

    const int ry = (tid >> 4) << 1;
    const int rx = (tid & 15) << 2;
    float acc[2][4] = {};

    #pragma unroll
    for (int k = 0; k < 64; k++) {
        float2 a  = *(const float2*)&su_t[k][ry];
        float4 bq = *(const float4*)&sv_t[k][rx];
        acc[0][0] = fmaf(a.x, bq.x, acc[0][0]); acc[0][1] = fmaf(a.x, bq.y, acc[0][1]);
        acc[0][2] = fmaf(a.x, bq.z, acc[0][2]); acc[0][3] = fmaf(a.x, bq.w, acc[0][3]);
        acc[1][0] = fmaf(a.y, bq.x, acc[1][0]); acc[1][1] = fmaf(a.y, bq.y, acc[1][1]);
        acc[1][2] = fmaf(a.y, bq.z, acc[1][2]); acc[1][3] = fmaf(a.y, bq.w, acc[1][3]);
    }

    #pragma unroll
    for (int i = 0; i < 2; i++) {
        int base = (e * NN + n0 + ry + i) * NN + m0 + rx;
        float4 sp = *(const float4*)(supports + base);
        float4 o;
        o.x = fmaxf(sp.x + acc[i][0], 0.f);
        o.y = fmaxf(sp.y + acc[i][1], 0.f);
        o.z = fmaxf(sp.z + acc[i][2], 0.f);
        o.w = fmaxf(sp.w + acc[i][3], 0.f);
        *(float4*)(g_sup + base) = o;
    }
}

// ---------------------------------------------------------------------------
// Kernel C: fused main pass (R8 structure, BG=4, grid 2048, PDL-gated).
// RN=4 rows x BOTH experts; xd staged once for all BG batches;
// xm2 via 6 coalesced LDG.128 (pair-packed layout), issued before
// prev-batch writeout; 2 barriers per batch; invs pre-duplicated {iv,iv}.
// ---------------------------------------------------------------------------
__global__ void __launch_bounds__(256, 3)
main_kernel(float* __restrict__ out) {
    __shared__ ull ps[RN][256];                  // packed {e0,e1} partials, 8 KB
    __shared__ ull xd[BG * RN * Tt];             // packed {xn,xn}, all batches
    __shared__ ull invs0[2][RN];                 // {iv_e0, iv_e0}, dbl-buffered
    __shared__ ull invs1[2][RN];                 // {iv_e1, iv_e1}, dbl-buffered

    // PDL: gate on prep_kernel's writes (g_sup, g_nodesT, g_nodesP)
    cudaGridDependencySynchronize();

    const int tid  = threadIdx.x;
    const int lane = tid & 31;
    const int warp = tid >> 5;
    const int n0 = blockIdx.x * RN;
    const int b0 = blockIdx.y * BG;
    const int m0 = tid * 2;

    // sup (relu'd) in registers: batch-invariant, this thread's m-pair, both e
    ull sup0[RN], sup1[RN];
    #pragma unroll
    for (int r = 0; r < RN; r++) {
        sup0[r] = *(const ull*)(g_sup + (n0 + r) * NN + m0);
        sup1[r] = *(const ull*)(g_sup + NN * NN + (n0 + r) * NN + m0);
    }

    // Stage duplicated row-node tables for ALL batches (192 entries)
    if (tid < BG * RN * Tt) {
        int bl  = tid / (RN * Tt);
        int rem = tid - bl * (RN * Tt);
        int r = rem / Tt, t = rem - r * Tt;
        float xv = g_nodesT[(b0 + bl) * (NN * Tt) + (n0 + r) * Tt + t];
        xd[tid] = pack2(xv, xv);
    }
    __syncthreads();

    // 2 * (ln2^-1)^2
    const float C = 4.1627379620112154f;
    const ull CM = pack2(-C, -C);
    const ull CP = pack2( C,  C);

    ull val0[RN], val1[RN];

    for (int bi = 0; bi < BG; ++bi) {
        // 1) this batch's xm2: 6 coalesced LDG.128 (pair-packed, 2 t's each)
        ull xm2[Tt];
        {
            const ulonglong2* xb =
                (const ulonglong2*)g_nodesP + (b0 + bi) * (6 * 256) + tid;
            #pragma unroll
            for (int j = 0; j < 6; j++) {
                ulonglong2 q = xb[j * 256];
                xm2[2 * j]     = q.x;
                xm2[2 * j + 1] = q.y;
            }
        }

        // 2) previous batch's writeout in the LDG shadow
        if (bi > 0) {
            const int pv = (bi - 1) & 1;
            float* ob = out + ((b0 + bi - 1) * NN + n0) * NN + m0;
            #pragma unroll
            for (int r = 0; r < RN; r++) {
                *(ull*)(ob + r * NN)        = mul2_(val0[r], invs0[pv][r]);
                *(ull*)(ob + ESTR + r * NN) = mul2_(val1[r], invs1[pv][r]);
            }
        }

        // 3) compute vals + packed partial sums
        #pragma unroll
        for (int r = 0; r < RN; r++) {
            const ulonglong2* xdp = (const ulonglong2*)&xd[(bi * RN + r) * Tt];
            ulonglong2 q0 = xdp[0], q1 = xdp[1], q2 = xdp[2];
            ulonglong2 q3 = xdp[3], q4 = xdp[4], q5 = xdp[5];
            ull pa = mul2_(xm2[0], q0.x);
            ull pb = mul2_(xm2[1], q0.y);
            pa = fma2_(xm2[2],  q1.x, pa);  pb = fma2_(xm2[3],  q1.y, pb);
            pa = fma2_(xm2[4],  q2.x, pa);  pb = fma2_(xm2[5],  q2.y, pb);
            pa = fma2_(xm2[6],  q3.x, pa);  pb = fma2_(xm2[7],  q3.y, pb);
            pa = fma2_(xm2[8],  q4.x, pa);  pb = fma2_(xm2[9],  q4.y, pb);
            pa = fma2_(xm2[10], q5.x, pa);  pb = fma2_(xm2[11], q5.y, pb);
            ull inner2 = add2_(pa, pb);
            ull d2p = fma2_(inner2, CM, CP);  // (1.4427*d)^2 packed
            float d20, d21;
            unpack2(d2p, d20, d21);
            d20 = fmaxf(d20, 0.f);
            d21 = fmaxf(d21, 0.f);
            float f0 = ex2_neg(sqrt_ap(d20)) + 1.0f;
            float f1 = ex2_neg(sqrt_ap(d21)) + 1.0f;
            ull fp = pack2(f0, f1);

            val0[r] = mul2_(fp, sup0[r]);
            val1[r] = mul2_(fp, sup1[r]);
            ps[r][tid] = pack2(hadd2(val0[r]), hadd2(val1[r]));
        }
        __syncthreads();   // ps ready

        // 4) packed reduction: warps 0..RN-1 each reduce one row (256 ulls)
        if (warp < RN) {
            const ulonglong2* p = (const ulonglong2*)ps[warp];
            ulonglong2 a0 = p[lane];
            ulonglong2 a1 = p[lane + 32];
            ulonglong2 a2 = p[lane + 64];
            ulonglong2 a3 = p[lane + 96];
            ull s01 = add2_(add2_(a0.x, a0.y), add2_(a1.x, a1.y));
            ull s23 = add2_(add2_(a2.x, a2.y), add2_(a3.x, a3.y));
            ull sum = add2_(s01, s23);
            #pragma unroll
            for (int o = 16; o > 0; o >>= 1)
                sum = add2_(sum, shfl_xor64(sum, o));
            if (lane == 0) {
                float s0, s1;
                unpack2(sum, s0, s1);
                float i0 = rcp_ap(fmaxf(s0, 1e-12f));
                float i1 = rcp_ap(fmaxf(s1, 1e-12f));
                invs0[bi & 1][warp] = pack2(i0, i0);
                invs1[bi & 1][warp] = pack2(i1, i1);
            }
        }
        __syncthreads();   // invs ready; guards ps reuse next iter
    }

    // Epilogue: last batch's writeout
    {
        const int pv = (BG - 1) & 1;
        float* ob = out + ((b0 + BG - 1) * NN + n0) * NN + m0;
        #pragma unroll
        for (int r = 0; r < RN; r++) {
            *(ull*)(ob + r * NN)        = mul2_(val0[r], invs0[pv][r]);
            *(ull*)(ob + ESTR + r * NN) = mul2_(val1[r], invs1[pv][r]);
        }
    }
}

// ---------------------------------------------------------------------------
extern "C" void kernel_launch(void* const* d_in, const int* in_sizes, int n_in,
                              void* d_out, int out_size) {
    const float* supports = (const float*)d_in[0];  // [2,512,512]
    const float* u        = (const float*)d_in[1];  // [2,512,64]
    const float* s        = (const float*)d_in[2];  // [2,64]
    const float* v        = (const float*)d_in[3];  // [2,512,64]
    const float* bias     = (const float*)d_in[4];  // [2,64]
    const float* inputs   = (const float*)d_in[5];  // [64,12,512,2]
    float* out = (float*)d_out;                     // [2,64,512,512]

    prep_kernel<<<dim3(8, 8, 3), 512>>>(supports, u, s, v, bias, inputs);

    // PDL launch: main may ramp while prep drains; in-kernel
    // cudaGridDependencySynchronize() gates consumption of prep outputs.
    cudaLaunchConfig_t cfg = {};
    cfg.gridDim  = dim3(NN / RN, Bn / BG);
    cfg.blockDim = dim3(256);
    cudaLaunchAttribute attr[1];
    attr[0].id = cudaLaunchAttributeProgrammaticStreamSerialization;
    attr[0].val.programmaticStreamSerializationAllowed = 1;
    cfg.attrs = attr;
    cfg.numAttrs = 1;
    cudaLaunchKernelEx(&cfg, main_kernel, out);
}